// round 9
// baseline (speedup 1.0000x reference)
#include <cuda_runtime.h>
#include <cuda_bf16.h>

#define NG    2048
#define W_IMG 128
#define H_IMG 128
#define HW    16384
#define NB    256         // blocks; capacity >=3/SM so all co-resident -> barrier safe
#define NT    256         // threads per block
#define NTILE 512         // 32 x 16 tiles of 4x8 px

// ---------------- scratch (static device globals) ----------------------------
__device__ float4 g_p0[NG], g_p1[NG];          // unsorted packed params
__device__ float2 g_p2[NG];                    // (cb, cullR)
__device__ unsigned long long g_key[NG];       // monotone depth key | index
__device__ float4 g_s0[NG], g_s1[NG];          // depth-sorted
__device__ float2 g_s2[NG];

__device__ unsigned g_barcnt = 0;
__device__ volatile unsigned g_bargen = 0;
__device__ int g_tilecnt = 0;

__device__ __forceinline__ void gridbar() {
    __syncthreads();
    if (threadIdx.x == 0) {
        unsigned gen = g_bargen;
        __threadfence();
        unsigned t = atomicAdd(&g_barcnt, 1u);
        if (t == NB - 1) {
            g_barcnt = 0;
            __threadfence();
            g_bargen = gen + 1;
        } else {
            while (g_bargen == gen) { __nanosleep(32); }
        }
    }
    __syncthreads();
}

__device__ __forceinline__ float ex2(float x) {
    float y; asm("ex2.approx.f32 %0, %1;" : "=f"(y) : "f"(x)); return y;
}
__device__ __forceinline__ float frcp(float x) {
    float y; asm("rcp.approx.f32 %0, %1;" : "=f"(y) : "f"(x)); return y;
}
__device__ __forceinline__ float sig_ap(float x) {
    return frcp(1.0f + ex2(-1.4426950408889634f * x));
}
__device__ __forceinline__ float exp_ap(float x) {
    return ex2(1.4426950408889634f * x);
}
__device__ __forceinline__ unsigned fkey(float f) {
    unsigned u = __float_as_uint(f);
    return (u & 0x80000000u) ? ~u : (u | 0x80000000u);
}

// smem: rank keys union per-warp blend buffers
union SmemU {
    unsigned long long sk[NG];                 // 16 KB (rank)
    struct {
        float4 b0[8][128];                     // 16 KB
        float4 b1[8][128];                     // 16 KB
        float  b2[8][128];                     //  4 KB
    } bl;
};

__global__ void __launch_bounds__(NT) k_fused(
        const float* __restrict__ pts, const float* __restrict__ scl,
        const float* __restrict__ col, const float* __restrict__ opa,
        const float* __restrict__ rot, const float* __restrict__ view,
        const float* __restrict__ proj, float* __restrict__ out)
{
    __shared__ SmemU sm;
    __shared__ float4 comb[8][32];
    __shared__ int s_tile;

    int tid = threadIdx.x;

    // reset dynamic tile counter (before first gridbar; phase 3 is after 2nd)
    if (blockIdx.x == 0 && tid == 0) g_tilecnt = 0;

    // ================= phase 1: prep (8 gaussians per block) =================
    if (tid < 8) {
        int i = blockIdx.x * 8 + tid;

        float v[16], pr[16];
#pragma unroll
        for (int k = 0; k < 16; k++) v[k]  = view[k];
#pragma unroll
        for (int k = 0; k < 16; k++) pr[k] = proj[k];

        float p0 = pts[3*i], p1 = pts[3*i+1], p2 = pts[3*i+2];

        float t0 = v[0]*p0 + v[1]*p1 + v[2]*p2  + v[3];
        float t1 = v[4]*p0 + v[5]*p1 + v[6]*p2  + v[7];
        float tz = v[8]*p0 + v[9]*p1 + v[10]*p2 + v[11];

        float q0 = rot[4*i], q1 = rot[4*i+1], q2 = rot[4*i+2], q3 = rot[4*i+3];
        float qn = rsqrtf(q0*q0 + q1*q1 + q2*q2 + q3*q3);
        q0 *= qn; q1 *= qn; q2 *= qn; q3 *= qn;
        float R0 = 1.f - 2.f*(q2*q2 + q3*q3), R1 = 2.f*(q1*q2 - q0*q3), R2 = 2.f*(q1*q3 + q0*q2);
        float R3 = 2.f*(q1*q2 + q0*q3), R4 = 1.f - 2.f*(q1*q1 + q3*q3), R5 = 2.f*(q2*q3 - q0*q1);
        float R6 = 2.f*(q1*q3 - q0*q2), R7 = 2.f*(q2*q3 + q0*q1), R8 = 1.f - 2.f*(q1*q1 + q2*q2);

        float s0 = exp_ap(scl[3*i]), s1 = exp_ap(scl[3*i+1]), s2 = exp_ap(scl[3*i+2]);
        float M0 = R0*s0, M1 = R1*s1, M2 = R2*s2;
        float M3 = R3*s0, M4 = R4*s1, M5 = R5*s2;
        float M6 = R6*s0, M7 = R7*s1, M8 = R8*s2;

        const float fx = 64.f, fy = 64.f;
        float invz = frcp(tz);
        float txz = fminf(fmaxf(t0*invz, -1.3f), 1.3f) * tz;
        float tyz = fminf(fmaxf(t1*invz, -1.3f), 1.3f) * tz;
        float J00 = fx*invz, J02 = -fx*txz*invz*invz;
        float J11 = fy*invz, J12 = -fy*tyz*invz*invz;

        float T00 = J00*v[0] + J02*v[8],  T01 = J00*v[1] + J02*v[9],  T02 = J00*v[2] + J02*v[10];
        float T10 = J11*v[4] + J12*v[8],  T11 = J11*v[5] + J12*v[9],  T12 = J11*v[6] + J12*v[10];

        float X00 = T00*M0 + T01*M3 + T02*M6;
        float X01 = T00*M1 + T01*M4 + T02*M7;
        float X02 = T00*M2 + T01*M5 + T02*M8;
        float X10 = T10*M0 + T11*M3 + T12*M6;
        float X11 = T10*M1 + T11*M4 + T12*M7;
        float X12 = T10*M2 + T11*M5 + T12*M8;

        float a = X00*X00 + X01*X01 + X02*X02 + 0.3f;
        float b = X00*X10 + X01*X11 + X02*X12;
        float c = X10*X10 + X11*X11 + X12*X12 + 0.3f;

        float det   = a*c - b*b;
        bool  valid = (tz > 0.2f) && (det > 0.0f);
        float det_s = (det > 0.0f) ? det : 1.0f;
        float idet  = frcp(det_s);

        const float L2E = 1.4426950408889634f;
        float A2 = -0.5f * c * idet * L2E;
        float C2 = -0.5f * a * idet * L2E;
        float Bq =         b * idet * L2E;

        float mid   = 0.5f * (a + c);
        float lam   = mid + sqrtf(fmaxf(mid*mid - det, 0.1f));
        float sq    = sqrtf(lam);
        float radii = valid ? ceilf(3.0f * sq) : 0.0f;
        float cullR = valid ? 3.3294f * sq : 0.0f;   // alpha<1/255 beyond this

        float fr0[4], fr1[4], fr3[4];
#pragma unroll
        for (int cc = 0; cc < 4; cc++) {
            fr0[cc] = pr[0]*v[cc]  + pr[1]*v[4+cc]  + pr[2]*v[8+cc]  + pr[3]*v[12+cc];
            fr1[cc] = pr[4]*v[cc]  + pr[5]*v[4+cc]  + pr[6]*v[8+cc]  + pr[7]*v[12+cc];
            fr3[cc] = pr[12]*v[cc] + pr[13]*v[4+cc] + pr[14]*v[8+cc] + pr[15]*v[12+cc];
        }
        float ph0 = fr0[0]*p0 + fr0[1]*p1 + fr0[2]*p2 + fr0[3];
        float ph1 = fr1[0]*p0 + fr1[1]*p1 + fr1[2]*p2 + fr1[3];
        float ph3 = fr3[0]*p0 + fr3[1]*p1 + fr3[2]*p2 + fr3[3];
        float pwn = frcp(ph3 + 1e-7f);
        float px  = ((ph0*pwn + 1.0f) * (float)W_IMG - 1.0f) * 0.5f;
        float py  = ((ph1*pwn + 1.0f) * (float)H_IMG - 1.0f) * 0.5f;

        float op = valid ? sig_ap(opa[i]) : 0.0f;
        float cr = sig_ap(col[3*i]);
        float cg = sig_ap(col[3*i+1]);
        float cb = sig_ap(col[3*i+2]);

        g_p0[i]  = make_float4(px, py, A2, Bq);
        g_p1[i]  = make_float4(C2, op, cr, cg);
        g_p2[i]  = make_float2(cb, cullR);
        g_key[i] = ((unsigned long long)fkey(tz) << 32) | (unsigned)i;

        out[3*HW + i]      = radii;
        out[3*HW + NG + i] = tz;
    }

    gridbar();

    // ================= phase 2: rank sort (1 warp per gaussian) ==============
    {
        for (int i = tid; i < NG; i += NT) sm.sk[i] = g_key[i];
        __syncthreads();

        int gt   = blockIdx.x * NT + tid;    // 65536 threads = 2048 warps
        int gi   = gt >> 5;
        int lane = tid & 31;
        unsigned long long ki = sm.sk[gi];

        int rk = 0;
#pragma unroll 16
        for (int it = 0; it < NG/32; it++) {
            rk += (sm.sk[32*it + lane] < ki) ? 1 : 0;
        }
        rk += __shfl_xor_sync(0xffffffffu, rk, 1);
        rk += __shfl_xor_sync(0xffffffffu, rk, 2);
        rk += __shfl_xor_sync(0xffffffffu, rk, 4);
        rk += __shfl_xor_sync(0xffffffffu, rk, 8);
        rk += __shfl_xor_sync(0xffffffffu, rk, 16);

        if (lane == 0) {
            g_s0[rk] = g_p0[gi];
            g_s1[rk] = g_p1[gi];
            g_s2[rk] = g_p2[gi];
        }
    }

    gridbar();

    // ========== phase 3: dynamic 4x8 tiles, warp = depth segment =============
    {
        int lane = tid & 31;
        int wid  = tid >> 5;                 // 0..7 : depth segment (256 gaussians)
        unsigned lmask = (1u << lane) - 1u;
        int base = wid * 256;

        for (;;) {
            if (tid == 0) s_tile = atomicAdd(&g_tilecnt, 1);
            __syncthreads();
            int t = s_tile;
            if (t >= NTILE) break;

            int tx = t & 31;                 // 32 tiles across (4 px)
            int ty = t >> 5;                 // 16 tiles down  (8 px)
            int pxi = tx * 4 + (lane & 3);
            int pyi = ty * 8 + (lane >> 2);
            float x = (float)pxi;
            float y = (float)pyi;
            float x0 = (float)(tx * 4), x1 = x0 + 3.f;
            float y0 = (float)(ty * 8), y1 = y0 + 7.f;

            float r = 0.f, g = 0.f, b = 0.f, T = 1.f;

            for (int sub = 0; sub < 2; sub++) {
                int sbase = base + sub * 128;

                // warp-local cull of 128 gaussians (4 per thread)
                float4 G0[4]; float4 G1[4]; float2 G2[4];
                unsigned mk[4];
#pragma unroll
                for (int k = 0; k < 4; k++) {
                    int gidx = sbase + k * 32 + lane;
                    G0[k] = g_s0[gidx]; G1[k] = g_s1[gidx]; G2[k] = g_s2[gidx];
                    float R  = G2[k].y;
                    float gx = G0[k].x, gy = G0[k].y;
                    // circle-vs-rect distance test (exact for circular cutoff)
                    float dxc = fmaxf(fmaxf(x0 - gx, gx - x1), 0.f);
                    float dyc = fmaxf(fmaxf(y0 - gy, gy - y1), 0.f);
                    bool p = (R > 0.f) && (dxc*dxc + dyc*dyc <= R*R);
                    mk[k] = __ballot_sync(0xffffffffu, p);
                }

                int pre = 0;
#pragma unroll
                for (int k = 0; k < 4; k++) {
                    unsigned m = mk[k];
                    if (m & (1u << lane)) {
                        int pos = pre + __popc(m & lmask);
                        sm.bl.b0[wid][pos] = G0[k];
                        sm.bl.b1[wid][pos] = G1[k];
                        sm.bl.b2[wid][pos] = G2[k].x;
                    }
                    pre += __popc(m);
                }
                int cnt = pre;
                __syncwarp();

#pragma unroll 4
                for (int n = 0; n < cnt; n++) {
                    float4 c0v = sm.bl.b0[wid][n];
                    float4 c1v = sm.bl.b1[wid][n];
                    float  cbv = sm.bl.b2[wid][n];
                    float dx = x - c0v.x;
                    float dy = y - c0v.y;
                    float pw = fmaf(c0v.z*dx, dx, fmaf(c1v.x*dy, dy, (c0v.w*dx)*dy));
                    float ee = ex2(pw);
                    float al = fminf(c1v.y * ee, 0.99f);
                    float w  = ((pw <= 0.0f) && (al >= 0.0039215686f)) ? T * al : 0.0f;
                    r = fmaf(w, c1v.z, r);
                    g = fmaf(w, c1v.w, g);
                    b = fmaf(w, cbv,  b);
                    T -= w;
                }
                __syncwarp();                 // buffer reused next sub-round
                if (__all_sync(0xffffffffu, T < 1e-4f)) break;  // segment saturated
            }

            comb[wid][lane] = make_float4(r, g, b, T);
            __syncthreads();

            if (wid == 0) {
                float Tt = 1.f, rr = 0.f, gg = 0.f, bb = 0.f;
#pragma unroll
                for (int s = 0; s < 8; s++) {
                    float4 f = comb[s][lane];
                    rr = fmaf(Tt, f.x, rr);
                    gg = fmaf(Tt, f.y, gg);
                    bb = fmaf(Tt, f.z, bb);
                    Tt *= f.w;
                }
                int p = pyi * W_IMG + pxi;
                out[p]        = rr;
                out[HW + p]   = gg;
                out[2*HW + p] = bb;
            }
            __syncthreads();                  // comb + s_tile reuse
        }
    }
}

// ---------------- launch -----------------------------------------------------
extern "C" void kernel_launch(void* const* d_in, const int* in_sizes, int n_in,
                              void* d_out, int out_size)
{
    const float* pts  = (const float*)d_in[0];
    const float* scl  = (const float*)d_in[1];
    const float* col  = (const float*)d_in[2];
    const float* opa  = (const float*)d_in[3];
    const float* rot  = (const float*)d_in[4];
    const float* view = (const float*)d_in[5];
    const float* proj = (const float*)d_in[6];
    float* out = (float*)d_out;

    k_fused<<<NB, NT>>>(pts, scl, col, opa, rot, view, proj, out);
}

// round 10
// speedup vs baseline: 1.0578x; 1.0578x over previous
#include <cuda_runtime.h>
#include <cuda_bf16.h>

#define NG    2048
#define W_IMG 128
#define H_IMG 128
#define HW    16384
#define NB    256         // blocks; 2/SM co-resident (smem-limited) -> barrier safe
#define NT    256         // threads per block

// ---------------- scratch (static device globals) ----------------------------
__device__ float4 g_p0[NG], g_p1[NG];          // unsorted packed params
__device__ float2 g_p2[NG];                    // (cb, cullR)
__device__ unsigned long long g_key[NG];       // monotone depth key | index
__device__ float4 g_s0[NG], g_s1[NG];          // depth-sorted
__device__ float2 g_s2[NG];

__device__ unsigned g_barcnt = 0;
__device__ volatile unsigned g_bargen = 0;

__device__ __forceinline__ void gridbar() {
    __syncthreads();
    if (threadIdx.x == 0) {
        unsigned gen = g_bargen;
        __threadfence();
        unsigned t = atomicAdd(&g_barcnt, 1u);
        if (t == NB - 1) {
            g_barcnt = 0;
            __threadfence();
            g_bargen = gen + 1;
        } else {
            while (g_bargen == gen) { __nanosleep(32); }
        }
    }
    __syncthreads();
}

__device__ __forceinline__ float ex2(float x) {
    float y; asm("ex2.approx.f32 %0, %1;" : "=f"(y) : "f"(x)); return y;
}
__device__ __forceinline__ float frcp(float x) {
    float y; asm("rcp.approx.f32 %0, %1;" : "=f"(y) : "f"(x)); return y;
}
__device__ __forceinline__ float sig_ap(float x) {
    return frcp(1.0f + ex2(-1.4426950408889634f * x));
}
__device__ __forceinline__ float exp_ap(float x) {
    return ex2(1.4426950408889634f * x);
}
__device__ __forceinline__ unsigned fkey(float f) {
    unsigned u = __float_as_uint(f);
    return (u & 0x80000000u) ? ~u : (u | 0x80000000u);
}

// dynamic smem layout: rank keys union blend quarter-buffers (512 entries each)
struct SmemBlend {
    float4 qb0[4][512];                        // 32 KB
    float4 qb1[4][512];                        // 32 KB
    float  qb2[4][512];                        //  8 KB
};
union SmemU {
    unsigned long long sk[NG];                 // 16 KB (rank)
    SmemBlend bl;                              // 72 KB (blend)
};
#define SMEM_BYTES (sizeof(SmemU))

__global__ void __launch_bounds__(NT) k_fused(
        const float* __restrict__ pts, const float* __restrict__ scl,
        const float* __restrict__ col, const float* __restrict__ opa,
        const float* __restrict__ rot, const float* __restrict__ view,
        const float* __restrict__ proj, float* __restrict__ out)
{
    extern __shared__ char dynsmem[];
    SmemU& sm = *reinterpret_cast<SmemU*>(dynsmem);
    __shared__ int    wcnt[4][16];             // per quarter: 8 k-groups x 2 warps
    __shared__ float4 comb[4][64];

    int tid = threadIdx.x;

    // ================= phase 1: prep (8 gaussians per block) =================
    if (tid < 8) {
        int i = blockIdx.x * 8 + tid;

        float v[16], pr[16];
#pragma unroll
        for (int k = 0; k < 16; k++) v[k]  = view[k];
#pragma unroll
        for (int k = 0; k < 16; k++) pr[k] = proj[k];

        float p0 = pts[3*i], p1 = pts[3*i+1], p2 = pts[3*i+2];

        float t0 = v[0]*p0 + v[1]*p1 + v[2]*p2  + v[3];
        float t1 = v[4]*p0 + v[5]*p1 + v[6]*p2  + v[7];
        float tz = v[8]*p0 + v[9]*p1 + v[10]*p2 + v[11];

        float q0 = rot[4*i], q1 = rot[4*i+1], q2 = rot[4*i+2], q3 = rot[4*i+3];
        float qn = rsqrtf(q0*q0 + q1*q1 + q2*q2 + q3*q3);
        q0 *= qn; q1 *= qn; q2 *= qn; q3 *= qn;
        float R0 = 1.f - 2.f*(q2*q2 + q3*q3), R1 = 2.f*(q1*q2 - q0*q3), R2 = 2.f*(q1*q3 + q0*q2);
        float R3 = 2.f*(q1*q2 + q0*q3), R4 = 1.f - 2.f*(q1*q1 + q3*q3), R5 = 2.f*(q2*q3 - q0*q1);
        float R6 = 2.f*(q1*q3 - q0*q2), R7 = 2.f*(q2*q3 + q0*q1), R8 = 1.f - 2.f*(q1*q1 + q2*q2);

        float s0 = exp_ap(scl[3*i]), s1 = exp_ap(scl[3*i+1]), s2 = exp_ap(scl[3*i+2]);
        float M0 = R0*s0, M1 = R1*s1, M2 = R2*s2;
        float M3 = R3*s0, M4 = R4*s1, M5 = R5*s2;
        float M6 = R6*s0, M7 = R7*s1, M8 = R8*s2;

        const float fx = 64.f, fy = 64.f;
        float invz = frcp(tz);
        float txz = fminf(fmaxf(t0*invz, -1.3f), 1.3f) * tz;
        float tyz = fminf(fmaxf(t1*invz, -1.3f), 1.3f) * tz;
        float J00 = fx*invz, J02 = -fx*txz*invz*invz;
        float J11 = fy*invz, J12 = -fy*tyz*invz*invz;

        float T00 = J00*v[0] + J02*v[8],  T01 = J00*v[1] + J02*v[9],  T02 = J00*v[2] + J02*v[10];
        float T10 = J11*v[4] + J12*v[8],  T11 = J11*v[5] + J12*v[9],  T12 = J11*v[6] + J12*v[10];

        float X00 = T00*M0 + T01*M3 + T02*M6;
        float X01 = T00*M1 + T01*M4 + T02*M7;
        float X02 = T00*M2 + T01*M5 + T02*M8;
        float X10 = T10*M0 + T11*M3 + T12*M6;
        float X11 = T10*M1 + T11*M4 + T12*M7;
        float X12 = T10*M2 + T11*M5 + T12*M8;

        float a = X00*X00 + X01*X01 + X02*X02 + 0.3f;
        float b = X00*X10 + X01*X11 + X02*X12;
        float c = X10*X10 + X11*X11 + X12*X12 + 0.3f;

        float det   = a*c - b*b;
        bool  valid = (tz > 0.2f) && (det > 0.0f);
        float det_s = (det > 0.0f) ? det : 1.0f;
        float idet  = frcp(det_s);

        const float L2E = 1.4426950408889634f;
        float A2 = -0.5f * c * idet * L2E;
        float C2 = -0.5f * a * idet * L2E;
        float Bq =         b * idet * L2E;

        float mid   = 0.5f * (a + c);
        float lam   = mid + sqrtf(fmaxf(mid*mid - det, 0.1f));
        float sq    = sqrtf(lam);
        float radii = valid ? ceilf(3.0f * sq) : 0.0f;
        float cullR = valid ? 3.3294f * sq : 0.0f;   // alpha<1/255 beyond this

        float fr0[4], fr1[4], fr3[4];
#pragma unroll
        for (int cc = 0; cc < 4; cc++) {
            fr0[cc] = pr[0]*v[cc]  + pr[1]*v[4+cc]  + pr[2]*v[8+cc]  + pr[3]*v[12+cc];
            fr1[cc] = pr[4]*v[cc]  + pr[5]*v[4+cc]  + pr[6]*v[8+cc]  + pr[7]*v[12+cc];
            fr3[cc] = pr[12]*v[cc] + pr[13]*v[4+cc] + pr[14]*v[8+cc] + pr[15]*v[12+cc];
        }
        float ph0 = fr0[0]*p0 + fr0[1]*p1 + fr0[2]*p2 + fr0[3];
        float ph1 = fr1[0]*p0 + fr1[1]*p1 + fr1[2]*p2 + fr1[3];
        float ph3 = fr3[0]*p0 + fr3[1]*p1 + fr3[2]*p2 + fr3[3];
        float pwn = frcp(ph3 + 1e-7f);
        float px  = ((ph0*pwn + 1.0f) * (float)W_IMG - 1.0f) * 0.5f;
        float py  = ((ph1*pwn + 1.0f) * (float)H_IMG - 1.0f) * 0.5f;

        float op = valid ? sig_ap(opa[i]) : 0.0f;
        float cr = sig_ap(col[3*i]);
        float cg = sig_ap(col[3*i+1]);
        float cb = sig_ap(col[3*i+2]);

        g_p0[i]  = make_float4(px, py, A2, Bq);
        g_p1[i]  = make_float4(C2, op, cr, cg);
        g_p2[i]  = make_float2(cb, cullR);
        g_key[i] = ((unsigned long long)fkey(tz) << 32) | (unsigned)i;

        out[3*HW + i]      = radii;
        out[3*HW + NG + i] = tz;
    }

    gridbar();

    // ================= phase 2: rank sort (1 warp per gaussian) ==============
    {
        for (int i = tid; i < NG; i += NT) sm.sk[i] = g_key[i];
        __syncthreads();

        int gt   = blockIdx.x * NT + tid;    // 65536 threads = 2048 warps
        int gi   = gt >> 5;
        int lane = tid & 31;
        unsigned long long ki = sm.sk[gi];

        int rk = 0;
#pragma unroll 16
        for (int it = 0; it < NG/32; it++) {
            rk += (sm.sk[32*it + lane] < ki) ? 1 : 0;
        }
        rk += __shfl_xor_sync(0xffffffffu, rk, 1);
        rk += __shfl_xor_sync(0xffffffffu, rk, 2);
        rk += __shfl_xor_sync(0xffffffffu, rk, 4);
        rk += __shfl_xor_sync(0xffffffffu, rk, 8);
        rk += __shfl_xor_sync(0xffffffffu, rk, 16);

        if (lane == 0) {
            g_s0[rk] = g_p0[gi];
            g_s1[rk] = g_p1[gi];
            g_s2[rk] = g_p2[gi];
        }
    }

    gridbar();

    // ===== phase 3: blend, 8x8 tile per block, 4-way depth split, 1 round ====
    {
        int lane = tid & 31;
        int qtr  = tid >> 6;                 // 0..3 : gaussian quarter (512 each)
        int wiq  = (tid >> 5) & 1;           // warp within quarter (0/1)
        int pix  = tid & 63;                 // pixel within 8x8 tile

        int tx = blockIdx.x & 15;            // 16 tiles across
        int ty = blockIdx.x >> 4;            // 16 tiles down
        int pxi = tx * 8 + (pix & 7);
        int pyi = ty * 8 + (pix >> 3);
        float x = (float)pxi;
        float y = (float)pyi;
        float x0 = (float)(tx * 8), x1 = x0 + 7.f;
        float y0 = (float)(ty * 8), y1 = y0 + 7.f;

        int base0 = qtr * 512;

        // ---- pass 1: light cull (px,py,R only), 8 gaussians per thread ----
        unsigned mk[8];
#pragma unroll
        for (int k = 0; k < 8; k++) {
            int gidx = base0 + k * 64 + wiq * 32 + lane;
            float2 c  = make_float2(g_s0[gidx].x, g_s0[gidx].y);
            float  R  = g_s2[gidx].y;
            // circle-vs-rect: exact for the circular alpha cutoff
            float dxc = fmaxf(fmaxf(x0 - c.x, c.x - x1), 0.f);
            float dyc = fmaxf(fmaxf(y0 - c.y, c.y - y1), 0.f);
            bool p = (R > 0.f) && (dxc*dxc + dyc*dyc <= R*R);
            mk[k] = __ballot_sync(0xffffffffu, p);
            if (lane == 0) wcnt[qtr][k * 2 + wiq] = __popc(mk[k]);
        }
        __syncthreads();

        // exclusive prefix over 16 (k, wiq) groups, depth order preserved
        int cnts[16];
#pragma unroll
        for (int j = 0; j < 16; j++) cnts[j] = wcnt[qtr][j];
        int cnt = 0;
#pragma unroll
        for (int j = 0; j < 16; j++) cnt += cnts[j];

        // ---- pass 2: reload survivors (L1-hot) and scatter ----
#pragma unroll
        for (int k = 0; k < 8; k++) {
            int my = k * 2 + wiq;
            int pre = 0;
#pragma unroll
            for (int j = 0; j < 16; j++) if (j < my) pre += cnts[j];
            unsigned m = mk[k];
            if (m & (1u << lane)) {
                int gidx = base0 + k * 64 + wiq * 32 + lane;
                int pos  = pre + __popc(m & ((1u << lane) - 1u));
                sm.bl.qb0[qtr][pos] = g_s0[gidx];
                sm.bl.qb1[qtr][pos] = g_s1[gidx];
                sm.bl.qb2[qtr][pos] = g_s2[gidx].x;
            }
        }
        __syncthreads();

        // ---- blend survivors front-to-back within quarter ----
        float r = 0.f, g = 0.f, b = 0.f, T = 1.f;
#pragma unroll 4
        for (int n = 0; n < cnt; n++) {
            float4 c0v = sm.bl.qb0[qtr][n];
            float4 c1v = sm.bl.qb1[qtr][n];
            float  cbv = sm.bl.qb2[qtr][n];
            float dx = x - c0v.x;
            float dy = y - c0v.y;
            float pw = fmaf(c0v.z*dx, dx, fmaf(c1v.x*dy, dy, (c0v.w*dx)*dy));
            float ee = ex2(pw);
            float al = fminf(c1v.y * ee, 0.99f);
            float w  = ((pw <= 0.0f) && (al >= 0.0039215686f)) ? T * al : 0.0f;
            r = fmaf(w, c1v.z, r);
            g = fmaf(w, c1v.w, g);
            b = fmaf(w, cbv,  b);
            T -= w;
        }

        // combine quarters: total = c0 + T0*(c1 + T1*(c2 + T2*c3))
        comb[qtr][pix] = make_float4(r, g, b, T);
        __syncthreads();
        if (qtr == 0) {
            float4 c1 = comb[1][pix];
            float4 c2 = comb[2][pix];
            float4 c3 = comb[3][pix];
            float rr = r + T * (c1.x + c1.w * (c2.x + c2.w * c3.x));
            float gg = g + T * (c1.y + c1.w * (c2.y + c2.w * c3.y));
            float bb = b + T * (c1.z + c1.w * (c2.z + c2.w * c3.z));
            int p = pyi * W_IMG + pxi;
            out[p]        = rr;
            out[HW + p]   = gg;
            out[2*HW + p] = bb;
        }
    }
}

// ---------------- launch -----------------------------------------------------
extern "C" void kernel_launch(void* const* d_in, const int* in_sizes, int n_in,
                              void* d_out, int out_size)
{
    const float* pts  = (const float*)d_in[0];
    const float* scl  = (const float*)d_in[1];
    const float* col  = (const float*)d_in[2];
    const float* opa  = (const float*)d_in[3];
    const float* rot  = (const float*)d_in[4];
    const float* view = (const float*)d_in[5];
    const float* proj = (const float*)d_in[6];
    float* out = (float*)d_out;

    static bool attr_set = false;
    if (!attr_set) {
        cudaFuncSetAttribute(k_fused, cudaFuncAttributeMaxDynamicSharedMemorySize,
                             (int)SMEM_BYTES);
        attr_set = true;
    }
    k_fused<<<NB, NT, SMEM_BYTES>>>(pts, scl, col, opa, rot, view, proj, out);
}

// round 11
// speedup vs baseline: 1.1109x; 1.0503x over previous
#include <cuda_runtime.h>
#include <cuda_bf16.h>

#define NG    2048
#define W_IMG 128
#define H_IMG 128
#define HW    16384
#define NB    256         // blocks; 2/SM co-resident (smem-limited) -> barrier safe
#define NT    256         // threads per block

// ---------------- scratch (static device globals) ----------------------------
__device__ float4 g_p0[NG], g_p1[NG];          // unsorted packed params
__device__ float2 g_p2[NG];                    // (cb, cullR)
__device__ unsigned long long g_key[NG];       // monotone depth key | index
__device__ float4 g_s0[NG], g_s1[NG];          // depth-sorted params
__device__ float4 g_c[NG];                     // depth-sorted (px,py,R,cb) for cull

__device__ unsigned g_barcnt = 0;
__device__ volatile unsigned g_bargen = 0;

__device__ __forceinline__ void gridbar() {
    __syncthreads();
    if (threadIdx.x == 0) {
        unsigned gen = g_bargen;
        __threadfence();
        unsigned t = atomicAdd(&g_barcnt, 1u);
        if (t == NB - 1) {
            g_barcnt = 0;
            __threadfence();
            g_bargen = gen + 1;
        } else {
            while (g_bargen == gen) { __nanosleep(32); }
        }
    }
    __syncthreads();
}

__device__ __forceinline__ float ex2(float x) {
    float y; asm("ex2.approx.f32 %0, %1;" : "=f"(y) : "f"(x)); return y;
}
__device__ __forceinline__ float frcp(float x) {
    float y; asm("rcp.approx.f32 %0, %1;" : "=f"(y) : "f"(x)); return y;
}
__device__ __forceinline__ float sig_ap(float x) {
    return frcp(1.0f + ex2(-1.4426950408889634f * x));
}
__device__ __forceinline__ float exp_ap(float x) {
    return ex2(1.4426950408889634f * x);
}
__device__ __forceinline__ unsigned fkey(float f) {
    unsigned u = __float_as_uint(f);
    return (u & 0x80000000u) ? ~u : (u | 0x80000000u);
}

// dynamic smem: rank keys union per-warp blend buffers (8 segs x 256 entries)
struct SmemBlend {
    float4 b0[8][256];                         // 32 KB
    float4 b1[8][256];                         // 32 KB
    float  b2[8][256];                         //  8 KB
};
union SmemU {
    unsigned long long sk[NG];                 // 16 KB (rank)
    SmemBlend bl;                              // 72 KB (blend)
};
#define SMEM_BYTES (sizeof(SmemU))

__global__ void __launch_bounds__(NT) k_fused(
        const float* __restrict__ pts, const float* __restrict__ scl,
        const float* __restrict__ col, const float* __restrict__ opa,
        const float* __restrict__ rot, const float* __restrict__ view,
        const float* __restrict__ proj, float* __restrict__ out)
{
    extern __shared__ char dynsmem[];
    SmemU& sm = *reinterpret_cast<SmemU*>(dynsmem);
    __shared__ float4 comb[8][64];             // 8 KB static

    int tid = threadIdx.x;

    // ================= phase 1: prep (8 gaussians per block) =================
    if (tid < 8) {
        int i = blockIdx.x * 8 + tid;

        float v[16], pr[16];
#pragma unroll
        for (int k = 0; k < 16; k++) v[k]  = view[k];
#pragma unroll
        for (int k = 0; k < 16; k++) pr[k] = proj[k];

        float p0 = pts[3*i], p1 = pts[3*i+1], p2 = pts[3*i+2];

        float t0 = v[0]*p0 + v[1]*p1 + v[2]*p2  + v[3];
        float t1 = v[4]*p0 + v[5]*p1 + v[6]*p2  + v[7];
        float tz = v[8]*p0 + v[9]*p1 + v[10]*p2 + v[11];

        float q0 = rot[4*i], q1 = rot[4*i+1], q2 = rot[4*i+2], q3 = rot[4*i+3];
        float qn = rsqrtf(q0*q0 + q1*q1 + q2*q2 + q3*q3);
        q0 *= qn; q1 *= qn; q2 *= qn; q3 *= qn;
        float R0 = 1.f - 2.f*(q2*q2 + q3*q3), R1 = 2.f*(q1*q2 - q0*q3), R2 = 2.f*(q1*q3 + q0*q2);
        float R3 = 2.f*(q1*q2 + q0*q3), R4 = 1.f - 2.f*(q1*q1 + q3*q3), R5 = 2.f*(q2*q3 - q0*q1);
        float R6 = 2.f*(q1*q3 - q0*q2), R7 = 2.f*(q2*q3 + q0*q1), R8 = 1.f - 2.f*(q1*q1 + q2*q2);

        float s0 = exp_ap(scl[3*i]), s1 = exp_ap(scl[3*i+1]), s2 = exp_ap(scl[3*i+2]);
        float M0 = R0*s0, M1 = R1*s1, M2 = R2*s2;
        float M3 = R3*s0, M4 = R4*s1, M5 = R5*s2;
        float M6 = R6*s0, M7 = R7*s1, M8 = R8*s2;

        const float fx = 64.f, fy = 64.f;
        float invz = frcp(tz);
        float txz = fminf(fmaxf(t0*invz, -1.3f), 1.3f) * tz;
        float tyz = fminf(fmaxf(t1*invz, -1.3f), 1.3f) * tz;
        float J00 = fx*invz, J02 = -fx*txz*invz*invz;
        float J11 = fy*invz, J12 = -fy*tyz*invz*invz;

        float T00 = J00*v[0] + J02*v[8],  T01 = J00*v[1] + J02*v[9],  T02 = J00*v[2] + J02*v[10];
        float T10 = J11*v[4] + J12*v[8],  T11 = J11*v[5] + J12*v[9],  T12 = J11*v[6] + J12*v[10];

        float X00 = T00*M0 + T01*M3 + T02*M6;
        float X01 = T00*M1 + T01*M4 + T02*M7;
        float X02 = T00*M2 + T01*M5 + T02*M8;
        float X10 = T10*M0 + T11*M3 + T12*M6;
        float X11 = T10*M1 + T11*M4 + T12*M7;
        float X12 = T10*M2 + T11*M5 + T12*M8;

        float a = X00*X00 + X01*X01 + X02*X02 + 0.3f;
        float b = X00*X10 + X01*X11 + X02*X12;
        float c = X10*X10 + X11*X11 + X12*X12 + 0.3f;

        float det   = a*c - b*b;
        bool  valid = (tz > 0.2f) && (det > 0.0f);
        float det_s = (det > 0.0f) ? det : 1.0f;
        float idet  = frcp(det_s);

        const float L2E = 1.4426950408889634f;
        float A2 = -0.5f * c * idet * L2E;
        float C2 = -0.5f * a * idet * L2E;
        float Bq =         b * idet * L2E;

        float mid   = 0.5f * (a + c);
        float lam   = mid + sqrtf(fmaxf(mid*mid - det, 0.1f));
        float sq    = sqrtf(lam);
        float radii = valid ? ceilf(3.0f * sq) : 0.0f;
        float cullR = valid ? 3.3294f * sq : 0.0f;   // alpha<1/255 beyond this

        float fr0[4], fr1[4], fr3[4];
#pragma unroll
        for (int cc = 0; cc < 4; cc++) {
            fr0[cc] = pr[0]*v[cc]  + pr[1]*v[4+cc]  + pr[2]*v[8+cc]  + pr[3]*v[12+cc];
            fr1[cc] = pr[4]*v[cc]  + pr[5]*v[4+cc]  + pr[6]*v[8+cc]  + pr[7]*v[12+cc];
            fr3[cc] = pr[12]*v[cc] + pr[13]*v[4+cc] + pr[14]*v[8+cc] + pr[15]*v[12+cc];
        }
        float ph0 = fr0[0]*p0 + fr0[1]*p1 + fr0[2]*p2 + fr0[3];
        float ph1 = fr1[0]*p0 + fr1[1]*p1 + fr1[2]*p2 + fr1[3];
        float ph3 = fr3[0]*p0 + fr3[1]*p1 + fr3[2]*p2 + fr3[3];
        float pwn = frcp(ph3 + 1e-7f);
        float px  = ((ph0*pwn + 1.0f) * (float)W_IMG - 1.0f) * 0.5f;
        float py  = ((ph1*pwn + 1.0f) * (float)H_IMG - 1.0f) * 0.5f;

        float op = valid ? sig_ap(opa[i]) : 0.0f;
        float cr = sig_ap(col[3*i]);
        float cg = sig_ap(col[3*i+1]);
        float cb = sig_ap(col[3*i+2]);

        g_p0[i]  = make_float4(px, py, A2, Bq);
        g_p1[i]  = make_float4(C2, op, cr, cg);
        g_p2[i]  = make_float2(cb, cullR);
        g_key[i] = ((unsigned long long)fkey(tz) << 32) | (unsigned)i;

        out[3*HW + i]      = radii;
        out[3*HW + NG + i] = tz;
    }

    gridbar();

    // ================= phase 2: rank sort (1 warp per gaussian) ==============
    {
        for (int i = tid; i < NG; i += NT) sm.sk[i] = g_key[i];
        __syncthreads();

        int gt   = blockIdx.x * NT + tid;    // 65536 threads = 2048 warps
        int gi   = gt >> 5;
        int lane = tid & 31;
        unsigned long long ki = sm.sk[gi];

        int rk = 0;
#pragma unroll 16
        for (int it = 0; it < NG/32; it++) {
            rk += (sm.sk[32*it + lane] < ki) ? 1 : 0;
        }
        rk += __shfl_xor_sync(0xffffffffu, rk, 1);
        rk += __shfl_xor_sync(0xffffffffu, rk, 2);
        rk += __shfl_xor_sync(0xffffffffu, rk, 4);
        rk += __shfl_xor_sync(0xffffffffu, rk, 8);
        rk += __shfl_xor_sync(0xffffffffu, rk, 16);

        if (lane == 0) {
            float4 p0v = g_p0[gi];
            float2 p2v = g_p2[gi];
            g_s0[rk] = p0v;
            g_s1[rk] = g_p1[gi];
            g_c[rk]  = make_float4(p0v.x, p0v.y, p2v.y, p2v.x);  // (px,py,R,cb)
        }
    }

    gridbar();

    // ==== phase 3: blend, 8x8 tile, warp = 256-gaussian depth segment ========
    {
        int lane = tid & 31;
        int wid  = tid >> 5;                 // 0..7 : depth segment
        unsigned lmask = (1u << lane) - 1u;
        int base = wid * 256;

        int tx = blockIdx.x & 15;            // 16 tiles across
        int ty = blockIdx.x >> 4;            // 16 tiles down
        // 2 pixels per lane, same column: rows (lane>>3) and (lane>>3)+4
        int col8 = lane & 7;
        int row8 = lane >> 3;
        int pxi  = tx * 8 + col8;
        int pyi0 = ty * 8 + row8;
        int pyi1 = pyi0 + 4;
        float x  = (float)pxi;
        float ya = (float)pyi0;
        float yb = (float)pyi1;
        float x0 = (float)(tx * 8), x1 = x0 + 7.f;
        float y0 = (float)(ty * 8), y1 = y0 + 7.f;

        // ---- warp-local cull: 8 gaussians per lane, one LDG.128 each ----
        unsigned mk[8];
#pragma unroll
        for (int k = 0; k < 8; k++) {
            int gidx = base + k * 32 + lane;
            float4 cc = g_c[gidx];           // (px,py,R,cb)
            float dxc = fmaxf(fmaxf(x0 - cc.x, cc.x - x1), 0.f);
            float dyc = fmaxf(fmaxf(y0 - cc.y, cc.y - y1), 0.f);
            bool p = (cc.z > 0.f) && (dxc*dxc + dyc*dyc <= cc.z*cc.z);
            mk[k] = __ballot_sync(0xffffffffu, p);
        }

        int pre = 0;
#pragma unroll
        for (int k = 0; k < 8; k++) {
            unsigned m = mk[k];
            if (m & (1u << lane)) {
                int gidx = base + k * 32 + lane;
                int pos  = pre + __popc(m & lmask);
                sm.bl.b0[wid][pos] = g_s0[gidx];
                sm.bl.b1[wid][pos] = g_s1[gidx];
                sm.bl.b2[wid][pos] = g_c[gidx].w;   // cb, L1-hot reload
            }
            pre += __popc(m);
        }
        int cnt = pre;
        __syncwarp();

        // ---- blend survivors for 2 pixels (independent T-chains) ----
        float ra = 0.f, ga = 0.f, ba = 0.f, Ta = 1.f;
        float rb = 0.f, gb = 0.f, bb = 0.f, Tb = 1.f;
#pragma unroll 2
        for (int n = 0; n < cnt; n++) {
            float4 c0v = sm.bl.b0[wid][n];
            float4 c1v = sm.bl.b1[wid][n];
            float  cbv = sm.bl.b2[wid][n];
            float dx   = x - c0v.x;
            float com  = (c0v.z * dx) * dx;   // A2*dx^2 shared
            float crs  = c0v.w * dx;          // Bq*dx  shared

            float dya = ya - c0v.y;
            float pwa = fmaf(c1v.x * dya, dya, fmaf(crs, dya, com));
            float ea  = ex2(pwa);
            float ala = fminf(c1v.y * ea, 0.99f);
            float wa  = ((pwa <= 0.0f) && (ala >= 0.0039215686f)) ? Ta * ala : 0.0f;
            ra = fmaf(wa, c1v.z, ra);
            ga = fmaf(wa, c1v.w, ga);
            ba = fmaf(wa, cbv,  ba);
            Ta -= wa;

            float dyb = yb - c0v.y;
            float pwb = fmaf(c1v.x * dyb, dyb, fmaf(crs, dyb, com));
            float eb  = ex2(pwb);
            float alb = fminf(c1v.y * eb, 0.99f);
            float wb  = ((pwb <= 0.0f) && (alb >= 0.0039215686f)) ? Tb * alb : 0.0f;
            rb = fmaf(wb, c1v.z, rb);
            gb = fmaf(wb, c1v.w, gb);
            bb = fmaf(wb, cbv,  bb);
            Tb -= wb;
        }

        // ---- combine 8 depth segments ----
        int pix0 = row8 * 8 + col8;           // 0..31
        int pix1 = pix0 + 32;                 // rows 4..7
        comb[wid][pix0] = make_float4(ra, ga, ba, Ta);
        comb[wid][pix1] = make_float4(rb, gb, bb, Tb);
        __syncthreads();

        if (wid == 0) {
#pragma unroll 2
            for (int h = 0; h < 2; h++) {
                int pix = lane + h * 32;
                float Tt = 1.f, rr = 0.f, gg = 0.f, bz = 0.f;
#pragma unroll
                for (int s = 0; s < 8; s++) {
                    float4 f = comb[s][pix];
                    rr = fmaf(Tt, f.x, rr);
                    gg = fmaf(Tt, f.y, gg);
                    bz = fmaf(Tt, f.z, bz);
                    Tt *= f.w;
                }
                int prow = ty * 8 + (pix >> 3);
                int pcol = tx * 8 + (pix & 7);
                int p = prow * W_IMG + pcol;
                out[p]        = rr;
                out[HW + p]   = gg;
                out[2*HW + p] = bz;
            }
        }
    }
}

// ---------------- launch -----------------------------------------------------
extern "C" void kernel_launch(void* const* d_in, const int* in_sizes, int n_in,
                              void* d_out, int out_size)
{
    const float* pts  = (const float*)d_in[0];
    const float* scl  = (const float*)d_in[1];
    const float* col  = (const float*)d_in[2];
    const float* opa  = (const float*)d_in[3];
    const float* rot  = (const float*)d_in[4];
    const float* view = (const float*)d_in[5];
    const float* proj = (const float*)d_in[6];
    float* out = (float*)d_out;

    static bool attr_set = false;
    if (!attr_set) {
        cudaFuncSetAttribute(k_fused, cudaFuncAttributeMaxDynamicSharedMemorySize,
                             (int)SMEM_BYTES);
        attr_set = true;
    }
    k_fused<<<NB, NT, SMEM_BYTES>>>(pts, scl, col, opa, rot, view, proj, out);
}

// round 12
// speedup vs baseline: 1.1128x; 1.0017x over previous
#include <cuda_runtime.h>
#include <cuda_bf16.h>

#define NG    2048
#define W_IMG 128
#define H_IMG 128
#define HW    16384
#define NB    256         // blocks; 2/SM co-resident (smem-limited) -> barrier safe
#define NT    256         // threads per block

// ---------------- scratch (static device globals) ----------------------------
__device__ float4 g_p0[NG], g_p1[NG];          // unsorted packed params
__device__ float2 g_p2[NG];                    // (cb, cullR)
__device__ unsigned long long g_key[NG];       // monotone depth key | index
__device__ float4 g_s0[NG], g_s1[NG];          // depth-sorted params
__device__ float4 g_c[NG];                     // depth-sorted (px,py,R,cb) for cull

__device__ unsigned g_barcnt = 0;
__device__ volatile unsigned g_bargen = 0;

__device__ __forceinline__ void gridbar() {
    __syncthreads();
    if (threadIdx.x == 0) {
        unsigned gen = g_bargen;
        __threadfence();
        unsigned t = atomicAdd(&g_barcnt, 1u);
        if (t == NB - 1) {
            g_barcnt = 0;
            __threadfence();
            g_bargen = gen + 1;
        } else {
            while (g_bargen == gen) { __nanosleep(32); }
        }
    }
    __syncthreads();
}

__device__ __forceinline__ float ex2(float x) {
    float y; asm("ex2.approx.f32 %0, %1;" : "=f"(y) : "f"(x)); return y;
}
__device__ __forceinline__ float frcp(float x) {
    float y; asm("rcp.approx.f32 %0, %1;" : "=f"(y) : "f"(x)); return y;
}
__device__ __forceinline__ float sig_ap(float x) {
    return frcp(1.0f + ex2(-1.4426950408889634f * x));
}
__device__ __forceinline__ float exp_ap(float x) {
    return ex2(1.4426950408889634f * x);
}
__device__ __forceinline__ unsigned fkey(float f) {
    unsigned u = __float_as_uint(f);
    return (u & 0x80000000u) ? ~u : (u | 0x80000000u);
}

// dynamic smem: rank keys union per-warp blend buffers (8 segs x 256 entries)
struct SmemBlend {
    float4 b0[8][256];                         // 32 KB
    float4 b1[8][256];                         // 32 KB
    float  b2[8][256];                         //  8 KB
};
union SmemU {
    unsigned long long sk[NG];                 // 16 KB (rank)
    SmemBlend bl;                              // 72 KB (blend)
};
#define SMEM_BYTES (sizeof(SmemU))

__global__ void __launch_bounds__(NT) k_fused(
        const float* __restrict__ pts, const float* __restrict__ scl,
        const float* __restrict__ col, const float* __restrict__ opa,
        const float* __restrict__ rot, const float* __restrict__ view,
        const float* __restrict__ proj, float* __restrict__ out)
{
    extern __shared__ char dynsmem[];
    SmemU& sm = *reinterpret_cast<SmemU*>(dynsmem);
    __shared__ float4 comb[8][64];             // 8 KB static

    int tid = threadIdx.x;

    // ================= phase 1: prep (8 gaussians per block) =================
    if (tid < 8) {
        int i = blockIdx.x * 8 + tid;

        float v[16], pr[16];
#pragma unroll
        for (int k = 0; k < 16; k++) v[k]  = view[k];
#pragma unroll
        for (int k = 0; k < 16; k++) pr[k] = proj[k];

        float p0 = pts[3*i], p1 = pts[3*i+1], p2 = pts[3*i+2];

        float t0 = v[0]*p0 + v[1]*p1 + v[2]*p2  + v[3];
        float t1 = v[4]*p0 + v[5]*p1 + v[6]*p2  + v[7];
        float tz = v[8]*p0 + v[9]*p1 + v[10]*p2 + v[11];

        float q0 = rot[4*i], q1 = rot[4*i+1], q2 = rot[4*i+2], q3 = rot[4*i+3];
        float qn = rsqrtf(q0*q0 + q1*q1 + q2*q2 + q3*q3);
        q0 *= qn; q1 *= qn; q2 *= qn; q3 *= qn;
        float R0 = 1.f - 2.f*(q2*q2 + q3*q3), R1 = 2.f*(q1*q2 - q0*q3), R2 = 2.f*(q1*q3 + q0*q2);
        float R3 = 2.f*(q1*q2 + q0*q3), R4 = 1.f - 2.f*(q1*q1 + q3*q3), R5 = 2.f*(q2*q3 - q0*q1);
        float R6 = 2.f*(q1*q3 - q0*q2), R7 = 2.f*(q2*q3 + q0*q1), R8 = 1.f - 2.f*(q1*q1 + q2*q2);

        float s0 = exp_ap(scl[3*i]), s1 = exp_ap(scl[3*i+1]), s2 = exp_ap(scl[3*i+2]);
        float M0 = R0*s0, M1 = R1*s1, M2 = R2*s2;
        float M3 = R3*s0, M4 = R4*s1, M5 = R5*s2;
        float M6 = R6*s0, M7 = R7*s1, M8 = R8*s2;

        const float fx = 64.f, fy = 64.f;
        float invz = frcp(tz);
        float txz = fminf(fmaxf(t0*invz, -1.3f), 1.3f) * tz;
        float tyz = fminf(fmaxf(t1*invz, -1.3f), 1.3f) * tz;
        float J00 = fx*invz, J02 = -fx*txz*invz*invz;
        float J11 = fy*invz, J12 = -fy*tyz*invz*invz;

        float T00 = J00*v[0] + J02*v[8],  T01 = J00*v[1] + J02*v[9],  T02 = J00*v[2] + J02*v[10];
        float T10 = J11*v[4] + J12*v[8],  T11 = J11*v[5] + J12*v[9],  T12 = J11*v[6] + J12*v[10];

        float X00 = T00*M0 + T01*M3 + T02*M6;
        float X01 = T00*M1 + T01*M4 + T02*M7;
        float X02 = T00*M2 + T01*M5 + T02*M8;
        float X10 = T10*M0 + T11*M3 + T12*M6;
        float X11 = T10*M1 + T11*M4 + T12*M7;
        float X12 = T10*M2 + T11*M5 + T12*M8;

        float a = X00*X00 + X01*X01 + X02*X02 + 0.3f;
        float b = X00*X10 + X01*X11 + X02*X12;
        float c = X10*X10 + X11*X11 + X12*X12 + 0.3f;

        float det   = a*c - b*b;
        bool  valid = (tz > 0.2f) && (det > 0.0f);
        float det_s = (det > 0.0f) ? det : 1.0f;
        float idet  = frcp(det_s);

        const float L2E = 1.4426950408889634f;
        float A2 = -0.5f * c * idet * L2E;
        float C2 = -0.5f * a * idet * L2E;
        float Bq =         b * idet * L2E;

        float mid   = 0.5f * (a + c);
        float lam   = mid + sqrtf(fmaxf(mid*mid - det, 0.1f));
        float sq    = sqrtf(lam);
        float radii = valid ? ceilf(3.0f * sq) : 0.0f;
        float cullR = valid ? 3.3294f * sq : 0.0f;   // alpha<1/255 beyond this

        float fr0[4], fr1[4], fr3[4];
#pragma unroll
        for (int cc = 0; cc < 4; cc++) {
            fr0[cc] = pr[0]*v[cc]  + pr[1]*v[4+cc]  + pr[2]*v[8+cc]  + pr[3]*v[12+cc];
            fr1[cc] = pr[4]*v[cc]  + pr[5]*v[4+cc]  + pr[6]*v[8+cc]  + pr[7]*v[12+cc];
            fr3[cc] = pr[12]*v[cc] + pr[13]*v[4+cc] + pr[14]*v[8+cc] + pr[15]*v[12+cc];
        }
        float ph0 = fr0[0]*p0 + fr0[1]*p1 + fr0[2]*p2 + fr0[3];
        float ph1 = fr1[0]*p0 + fr1[1]*p1 + fr1[2]*p2 + fr1[3];
        float ph3 = fr3[0]*p0 + fr3[1]*p1 + fr3[2]*p2 + fr3[3];
        float pwn = frcp(ph3 + 1e-7f);
        float px  = ((ph0*pwn + 1.0f) * (float)W_IMG - 1.0f) * 0.5f;
        float py  = ((ph1*pwn + 1.0f) * (float)H_IMG - 1.0f) * 0.5f;

        float op = valid ? sig_ap(opa[i]) : 0.0f;
        float cr = sig_ap(col[3*i]);
        float cg = sig_ap(col[3*i+1]);
        float cb = sig_ap(col[3*i+2]);

        g_p0[i]  = make_float4(px, py, A2, Bq);
        g_p1[i]  = make_float4(C2, op, cr, cg);
        g_p2[i]  = make_float2(cb, cullR);
        g_key[i] = ((unsigned long long)fkey(tz) << 32) | (unsigned)i;

        out[3*HW + i]      = radii;
        out[3*HW + NG + i] = tz;
    }

    gridbar();

    // ================= phase 2: rank sort (1 warp per gaussian) ==============
    {
        for (int i = tid; i < NG; i += NT) sm.sk[i] = g_key[i];
        __syncthreads();

        int gt   = blockIdx.x * NT + tid;    // 65536 threads = 2048 warps
        int gi   = gt >> 5;
        int lane = tid & 31;
        unsigned long long ki = sm.sk[gi];

        int rk = 0;
#pragma unroll 16
        for (int it = 0; it < NG/32; it++) {
            rk += (sm.sk[32*it + lane] < ki) ? 1 : 0;
        }
        rk += __shfl_xor_sync(0xffffffffu, rk, 1);
        rk += __shfl_xor_sync(0xffffffffu, rk, 2);
        rk += __shfl_xor_sync(0xffffffffu, rk, 4);
        rk += __shfl_xor_sync(0xffffffffu, rk, 8);
        rk += __shfl_xor_sync(0xffffffffu, rk, 16);

        if (lane == 0) {
            float4 p0v = g_p0[gi];
            float2 p2v = g_p2[gi];
            g_s0[rk] = p0v;
            g_s1[rk] = g_p1[gi];
            g_c[rk]  = make_float4(p0v.x, p0v.y, p2v.y, p2v.x);  // (px,py,R,cb)
        }
    }

    gridbar();

    // ==== phase 3: blend, 8x8 tile, warp = 256-gaussian depth segment ========
    // Density-aware block->tile permutation:
    //  - blocks 108..147 (alone on their SM under LUT[b%148]) get the 40
    //    densest (innermost) tiles;
    //  - paired blocks (b, b+148) get density ranks j and 215-j.
    {
        int bidx = blockIdx.x;
        int irk;                              // density rank: 0 = innermost tile
        if (bidx >= 108 && bidx < 148) irk = bidx - 108;
        else if (bidx < 108)           irk = bidx + 40;
        else                           irk = 403 - bidx;

        // ring k: 4k^2 <= irk < (2k+2)^2 ; perimeter walk for position
        int k = 0;
        while ((2*k + 2) * (2*k + 2) <= irk) k++;
        int pos = irk - 4*k*k;
        int lo = 7 - k, s = 2*k + 2, hi = lo + s - 1;
        int tx, ty;
        if (pos < s)               { ty = lo; tx = lo + pos; }
        else if (pos < 2*s - 1)    { tx = hi; ty = lo + 1 + (pos - s); }
        else if (pos < 3*s - 2)    { ty = hi; tx = hi - 1 - (pos - (2*s - 1)); }
        else                       { tx = lo; ty = hi - 1 - (pos - (3*s - 2)); }

        int lane = tid & 31;
        int wid  = tid >> 5;                 // 0..7 : depth segment
        unsigned lmask = (1u << lane) - 1u;
        int base = wid * 256;

        // 2 pixels per lane, same column: rows (lane>>3) and (lane>>3)+4
        int col8 = lane & 7;
        int row8 = lane >> 3;
        int pxi  = tx * 8 + col8;
        int pyi0 = ty * 8 + row8;
        float x  = (float)pxi;
        float ya = (float)pyi0;
        float yb = ya + 4.f;
        float x0 = (float)(tx * 8), x1 = x0 + 7.f;
        float y0 = (float)(ty * 8), y1 = y0 + 7.f;

        // ---- warp-local cull: 8 gaussians per lane, one LDG.128 each ----
        unsigned mk[8];
#pragma unroll
        for (int kk = 0; kk < 8; kk++) {
            int gidx = base + kk * 32 + lane;
            float4 cc = g_c[gidx];           // (px,py,R,cb)
            float dxc = fmaxf(fmaxf(x0 - cc.x, cc.x - x1), 0.f);
            float dyc = fmaxf(fmaxf(y0 - cc.y, cc.y - y1), 0.f);
            bool p = (cc.z > 0.f) && (dxc*dxc + dyc*dyc <= cc.z*cc.z);
            mk[kk] = __ballot_sync(0xffffffffu, p);
        }

        int pre = 0;
#pragma unroll
        for (int kk = 0; kk < 8; kk++) {
            unsigned m = mk[kk];
            if (m & (1u << lane)) {
                int gidx = base + kk * 32 + lane;
                int pp   = pre + __popc(m & lmask);
                sm.bl.b0[wid][pp] = g_s0[gidx];
                sm.bl.b1[wid][pp] = g_s1[gidx];
                sm.bl.b2[wid][pp] = g_c[gidx].w;   // cb, L1-hot reload
            }
            pre += __popc(m);
        }
        int cnt = pre;
        __syncwarp();

        // ---- blend survivors for 2 pixels (independent T-chains) ----
        float ra = 0.f, ga = 0.f, ba = 0.f, Ta = 1.f;
        float rb = 0.f, gb = 0.f, bb = 0.f, Tb = 1.f;
#pragma unroll 2
        for (int n = 0; n < cnt; n++) {
            float4 c0v = sm.bl.b0[wid][n];
            float4 c1v = sm.bl.b1[wid][n];
            float  cbv = sm.bl.b2[wid][n];
            float dx   = x - c0v.x;
            float com  = (c0v.z * dx) * dx;   // A2*dx^2 shared
            float crs  = c0v.w * dx;          // Bq*dx  shared

            float dya = ya - c0v.y;
            float pwa = fmaf(c1v.x * dya, dya, fmaf(crs, dya, com));
            float ea  = ex2(pwa);
            float ala = fminf(c1v.y * ea, 0.99f);
            float wa  = ((pwa <= 0.0f) && (ala >= 0.0039215686f)) ? Ta * ala : 0.0f;
            ra = fmaf(wa, c1v.z, ra);
            ga = fmaf(wa, c1v.w, ga);
            ba = fmaf(wa, cbv,  ba);
            Ta -= wa;

            float dyb = yb - c0v.y;
            float pwb = fmaf(c1v.x * dyb, dyb, fmaf(crs, dyb, com));
            float eb  = ex2(pwb);
            float alb = fminf(c1v.y * eb, 0.99f);
            float wb  = ((pwb <= 0.0f) && (alb >= 0.0039215686f)) ? Tb * alb : 0.0f;
            rb = fmaf(wb, c1v.z, rb);
            gb = fmaf(wb, c1v.w, gb);
            bb = fmaf(wb, cbv,  bb);
            Tb -= wb;
        }

        // ---- combine 8 depth segments ----
        int pix0 = row8 * 8 + col8;           // 0..31
        int pix1 = pix0 + 32;                 // rows 4..7
        comb[wid][pix0] = make_float4(ra, ga, ba, Ta);
        comb[wid][pix1] = make_float4(rb, gb, bb, Tb);
        __syncthreads();

        if (wid == 0) {
#pragma unroll 2
            for (int h = 0; h < 2; h++) {
                int pix = lane + h * 32;
                float Tt = 1.f, rr = 0.f, gg = 0.f, bz = 0.f;
#pragma unroll
                for (int ss = 0; ss < 8; ss++) {
                    float4 f = comb[ss][pix];
                    rr = fmaf(Tt, f.x, rr);
                    gg = fmaf(Tt, f.y, gg);
                    bz = fmaf(Tt, f.z, bz);
                    Tt *= f.w;
                }
                int prow = ty * 8 + (pix >> 3);
                int pcol = tx * 8 + (pix & 7);
                int p = prow * W_IMG + pcol;
                out[p]        = rr;
                out[HW + p]   = gg;
                out[2*HW + p] = bz;
            }
        }
    }
}

// ---------------- launch -----------------------------------------------------
extern "C" void kernel_launch(void* const* d_in, const int* in_sizes, int n_in,
                              void* d_out, int out_size)
{
    const float* pts  = (const float*)d_in[0];
    const float* scl  = (const float*)d_in[1];
    const float* col  = (const float*)d_in[2];
    const float* opa  = (const float*)d_in[3];
    const float* rot  = (const float*)d_in[4];
    const float* view = (const float*)d_in[5];
    const float* proj = (const float*)d_in[6];
    float* out = (float*)d_out;

    static bool attr_set = false;
    if (!attr_set) {
        cudaFuncSetAttribute(k_fused, cudaFuncAttributeMaxDynamicSharedMemorySize,
                             (int)SMEM_BYTES);
        attr_set = true;
    }
    k_fused<<<NB, NT, SMEM_BYTES>>>(pts, scl, col, opa, rot, view, proj, out);
}

// round 13
// speedup vs baseline: 1.2351x; 1.1098x over previous
#include <cuda_runtime.h>
#include <cuda_bf16.h>

#define NG    2048
#define W_IMG 128
#define H_IMG 128
#define HW    16384
#define NB    256         // blocks; 2/SM co-resident (88KB smem) -> barrier safe
#define NT    512         // threads per block -> 32 warps/SM = 8/SMSP

// ---------------- scratch (static device globals) ----------------------------
__device__ float4 g_p0[NG], g_p1[NG];          // unsorted packed params
__device__ float2 g_p2[NG];                    // (cb, cullR)
__device__ unsigned long long g_key[NG];       // monotone depth key | index
__device__ float4 g_s0[NG], g_s1[NG];          // depth-sorted params
__device__ float4 g_c[NG];                     // depth-sorted (px,py,R,cb) for cull

__device__ unsigned g_barcnt = 0;
__device__ volatile unsigned g_bargen = 0;

__device__ __forceinline__ void gridbar() {
    __syncthreads();
    if (threadIdx.x == 0) {
        unsigned gen = g_bargen;
        __threadfence();
        unsigned t = atomicAdd(&g_barcnt, 1u);
        if (t == NB - 1) {
            g_barcnt = 0;
            __threadfence();
            g_bargen = gen + 1;
        } else {
            while (g_bargen == gen) { __nanosleep(32); }
        }
    }
    __syncthreads();
}

__device__ __forceinline__ float ex2(float x) {
    float y; asm("ex2.approx.f32 %0, %1;" : "=f"(y) : "f"(x)); return y;
}
__device__ __forceinline__ float lg2(float x) {
    float y; asm("lg2.approx.f32 %0, %1;" : "=f"(y) : "f"(x)); return y;
}
__device__ __forceinline__ float frcp(float x) {
    float y; asm("rcp.approx.f32 %0, %1;" : "=f"(y) : "f"(x)); return y;
}
__device__ __forceinline__ float sig_ap(float x) {
    return frcp(1.0f + ex2(-1.4426950408889634f * x));
}
__device__ __forceinline__ float exp_ap(float x) {
    return ex2(1.4426950408889634f * x);
}
__device__ __forceinline__ unsigned fkey(float f) {
    unsigned u = __float_as_uint(f);
    return (u & 0x80000000u) ? ~u : (u | 0x80000000u);
}

// dynamic smem: rank keys union per-warp blend buffers (16 segs x 128 entries)
struct SmemBlend {
    float4 b0[16][128];                        // 32 KB
    float4 b1[16][128];                        // 32 KB
    float  b2[16][128];                        //  8 KB
};
union SmemU {
    unsigned long long sk[NG];                 // 16 KB (rank)
    SmemBlend bl;                              // 72 KB (blend)
};
#define SMEM_BYTES (sizeof(SmemU))

__global__ void __launch_bounds__(NT) k_fused(
        const float* __restrict__ pts, const float* __restrict__ scl,
        const float* __restrict__ col, const float* __restrict__ opa,
        const float* __restrict__ rot, const float* __restrict__ view,
        const float* __restrict__ proj, float* __restrict__ out)
{
    extern __shared__ char dynsmem[];
    SmemU& sm = *reinterpret_cast<SmemU*>(dynsmem);
    __shared__ float4 comb[16][64];            // 16 KB static

    int tid = threadIdx.x;

    // ================= phase 1: prep (8 gaussians per block) =================
    if (tid < 8) {
        int i = blockIdx.x * 8 + tid;

        float v[16], pr[16];
#pragma unroll
        for (int k = 0; k < 16; k++) v[k]  = view[k];
#pragma unroll
        for (int k = 0; k < 16; k++) pr[k] = proj[k];

        float p0 = pts[3*i], p1 = pts[3*i+1], p2 = pts[3*i+2];

        float t0 = v[0]*p0 + v[1]*p1 + v[2]*p2  + v[3];
        float t1 = v[4]*p0 + v[5]*p1 + v[6]*p2  + v[7];
        float tz = v[8]*p0 + v[9]*p1 + v[10]*p2 + v[11];

        float q0 = rot[4*i], q1 = rot[4*i+1], q2 = rot[4*i+2], q3 = rot[4*i+3];
        float qn = rsqrtf(q0*q0 + q1*q1 + q2*q2 + q3*q3);
        q0 *= qn; q1 *= qn; q2 *= qn; q3 *= qn;
        float R0 = 1.f - 2.f*(q2*q2 + q3*q3), R1 = 2.f*(q1*q2 - q0*q3), R2 = 2.f*(q1*q3 + q0*q2);
        float R3 = 2.f*(q1*q2 + q0*q3), R4 = 1.f - 2.f*(q1*q1 + q3*q3), R5 = 2.f*(q2*q3 - q0*q1);
        float R6 = 2.f*(q1*q3 - q0*q2), R7 = 2.f*(q2*q3 + q0*q1), R8 = 1.f - 2.f*(q1*q1 + q2*q2);

        float s0 = exp_ap(scl[3*i]), s1 = exp_ap(scl[3*i+1]), s2 = exp_ap(scl[3*i+2]);
        float M0 = R0*s0, M1 = R1*s1, M2 = R2*s2;
        float M3 = R3*s0, M4 = R4*s1, M5 = R5*s2;
        float M6 = R6*s0, M7 = R7*s1, M8 = R8*s2;

        const float fx = 64.f, fy = 64.f;
        float invz = frcp(tz);
        float txz = fminf(fmaxf(t0*invz, -1.3f), 1.3f) * tz;
        float tyz = fminf(fmaxf(t1*invz, -1.3f), 1.3f) * tz;
        float J00 = fx*invz, J02 = -fx*txz*invz*invz;
        float J11 = fy*invz, J12 = -fy*tyz*invz*invz;

        float T00 = J00*v[0] + J02*v[8],  T01 = J00*v[1] + J02*v[9],  T02 = J00*v[2] + J02*v[10];
        float T10 = J11*v[4] + J12*v[8],  T11 = J11*v[5] + J12*v[9],  T12 = J11*v[6] + J12*v[10];

        float X00 = T00*M0 + T01*M3 + T02*M6;
        float X01 = T00*M1 + T01*M4 + T02*M7;
        float X02 = T00*M2 + T01*M5 + T02*M8;
        float X10 = T10*M0 + T11*M3 + T12*M6;
        float X11 = T10*M1 + T11*M4 + T12*M7;
        float X12 = T10*M2 + T11*M5 + T12*M8;

        float a = X00*X00 + X01*X01 + X02*X02 + 0.3f;
        float b = X00*X10 + X01*X11 + X02*X12;
        float c = X10*X10 + X11*X11 + X12*X12 + 0.3f;

        float det   = a*c - b*b;
        bool  valid = (tz > 0.2f) && (det > 0.0f);
        float det_s = (det > 0.0f) ? det : 1.0f;
        float idet  = frcp(det_s);

        const float L2E = 1.4426950408889634f;
        float A2 = -0.5f * c * idet * L2E;
        float C2 = -0.5f * a * idet * L2E;
        float Bq =         b * idet * L2E;

        float mid   = 0.5f * (a + c);
        float lam   = mid + sqrtf(fmaxf(mid*mid - det, 0.1f));
        float sq    = sqrtf(lam);
        float radii = valid ? ceilf(3.0f * sq) : 0.0f;

        float op = valid ? sig_ap(opa[i]) : 0.0f;
        // opacity-aware cull radius: alpha = op*exp(-d^2/(2*lam)) < 1/255
        // beyond R = sqrt(2*ln(255*op))*sqrt(lam). ln = lg2*ln2.
        float lnt   = 0.6931471805599453f * lg2(255.0f * fmaxf(op, 1e-30f));
        float cullR = (valid && lnt > 0.f) ? 1.001f * sqrtf(2.0f * lnt) * sq : 0.0f;

        float fr0[4], fr1[4], fr3[4];
#pragma unroll
        for (int cc = 0; cc < 4; cc++) {
            fr0[cc] = pr[0]*v[cc]  + pr[1]*v[4+cc]  + pr[2]*v[8+cc]  + pr[3]*v[12+cc];
            fr1[cc] = pr[4]*v[cc]  + pr[5]*v[4+cc]  + pr[6]*v[8+cc]  + pr[7]*v[12+cc];
            fr3[cc] = pr[12]*v[cc] + pr[13]*v[4+cc] + pr[14]*v[8+cc] + pr[15]*v[12+cc];
        }
        float ph0 = fr0[0]*p0 + fr0[1]*p1 + fr0[2]*p2 + fr0[3];
        float ph1 = fr1[0]*p0 + fr1[1]*p1 + fr1[2]*p2 + fr1[3];
        float ph3 = fr3[0]*p0 + fr3[1]*p1 + fr3[2]*p2 + fr3[3];
        float pwn = frcp(ph3 + 1e-7f);
        float px  = ((ph0*pwn + 1.0f) * (float)W_IMG - 1.0f) * 0.5f;
        float py  = ((ph1*pwn + 1.0f) * (float)H_IMG - 1.0f) * 0.5f;

        float cr = sig_ap(col[3*i]);
        float cg = sig_ap(col[3*i+1]);
        float cb = sig_ap(col[3*i+2]);

        g_p0[i]  = make_float4(px, py, A2, Bq);
        g_p1[i]  = make_float4(C2, op, cr, cg);
        g_p2[i]  = make_float2(cb, cullR);
        g_key[i] = ((unsigned long long)fkey(tz) << 32) | (unsigned)i;

        out[3*HW + i]      = radii;
        out[3*HW + NG + i] = tz;
    }

    gridbar();

    // ========= phase 2: rank sort (first 8 warps/block, 1 warp/gaussian) =====
    {
        for (int i = tid; i < NG; i += NT) sm.sk[i] = g_key[i];
        __syncthreads();

        int wid  = tid >> 5;
        int lane = tid & 31;
        if (wid < 8) {
            int gi = blockIdx.x * 8 + wid;   // 256 blocks x 8 = 2048
            unsigned long long ki = sm.sk[gi];

            int rk = 0;
#pragma unroll 16
            for (int it = 0; it < NG/32; it++) {
                rk += (sm.sk[32*it + lane] < ki) ? 1 : 0;
            }
            rk += __shfl_xor_sync(0xffffffffu, rk, 1);
            rk += __shfl_xor_sync(0xffffffffu, rk, 2);
            rk += __shfl_xor_sync(0xffffffffu, rk, 4);
            rk += __shfl_xor_sync(0xffffffffu, rk, 8);
            rk += __shfl_xor_sync(0xffffffffu, rk, 16);

            if (lane == 0) {
                float4 p0v = g_p0[gi];
                float2 p2v = g_p2[gi];
                g_s0[rk] = p0v;
                g_s1[rk] = g_p1[gi];
                g_c[rk]  = make_float4(p0v.x, p0v.y, p2v.y, p2v.x);  // (px,py,R,cb)
            }
        }
    }

    gridbar();

    // ==== phase 3: blend, 8x8 tile, warp = 128-gaussian depth segment ========
    {
        int lane = tid & 31;
        int wid  = tid >> 5;                 // 0..15 : depth segment
        unsigned lmask = (1u << lane) - 1u;
        int base = wid * 128;

        int tx = blockIdx.x & 15;            // 16 tiles across
        int ty = blockIdx.x >> 4;            // 16 tiles down
        // 2 pixels per lane, same column: rows (lane>>3) and (lane>>3)+4
        int col8 = lane & 7;
        int row8 = lane >> 3;
        int pxi  = tx * 8 + col8;
        int pyi0 = ty * 8 + row8;
        float x  = (float)pxi;
        float ya = (float)pyi0;
        float yb = ya + 4.f;
        float x0 = (float)(tx * 8), x1 = x0 + 7.f;
        float y0 = (float)(ty * 8), y1 = y0 + 7.f;

        // ---- warp-local cull: 4 gaussians per lane, one LDG.128 each ----
        unsigned mk[4];
#pragma unroll
        for (int kk = 0; kk < 4; kk++) {
            int gidx = base + kk * 32 + lane;
            float4 cc = g_c[gidx];           // (px,py,R,cb)
            float dxc = fmaxf(fmaxf(x0 - cc.x, cc.x - x1), 0.f);
            float dyc = fmaxf(fmaxf(y0 - cc.y, cc.y - y1), 0.f);
            bool p = (cc.z > 0.f) && (dxc*dxc + dyc*dyc <= cc.z*cc.z);
            mk[kk] = __ballot_sync(0xffffffffu, p);
        }

        int pre = 0;
#pragma unroll
        for (int kk = 0; kk < 4; kk++) {
            unsigned m = mk[kk];
            if (m & (1u << lane)) {
                int gidx = base + kk * 32 + lane;
                int pp   = pre + __popc(m & lmask);
                sm.bl.b0[wid][pp] = g_s0[gidx];
                sm.bl.b1[wid][pp] = g_s1[gidx];
                sm.bl.b2[wid][pp] = g_c[gidx].w;   // cb, L1-hot reload
            }
            pre += __popc(m);
        }
        int cnt = pre;
        __syncwarp();

        // ---- blend survivors for 2 pixels (independent T-chains) ----
        float ra = 0.f, ga = 0.f, ba = 0.f, Ta = 1.f;
        float rb = 0.f, gb = 0.f, bb = 0.f, Tb = 1.f;
#pragma unroll 2
        for (int n = 0; n < cnt; n++) {
            float4 c0v = sm.bl.b0[wid][n];
            float4 c1v = sm.bl.b1[wid][n];
            float  cbv = sm.bl.b2[wid][n];
            float dx   = x - c0v.x;
            float com  = (c0v.z * dx) * dx;   // A2*dx^2 shared
            float crs  = c0v.w * dx;          // Bq*dx  shared

            float dya = ya - c0v.y;
            float pwa = fmaf(c1v.x * dya, dya, fmaf(crs, dya, com));
            float ea  = ex2(pwa);
            float ala = fminf(c1v.y * ea, 0.99f);
            float wa  = ((pwa <= 0.0f) && (ala >= 0.0039215686f)) ? Ta * ala : 0.0f;
            ra = fmaf(wa, c1v.z, ra);
            ga = fmaf(wa, c1v.w, ga);
            ba = fmaf(wa, cbv,  ba);
            Ta -= wa;

            float dyb = yb - c0v.y;
            float pwb = fmaf(c1v.x * dyb, dyb, fmaf(crs, dyb, com));
            float eb  = ex2(pwb);
            float alb = fminf(c1v.y * eb, 0.99f);
            float wb  = ((pwb <= 0.0f) && (alb >= 0.0039215686f)) ? Tb * alb : 0.0f;
            rb = fmaf(wb, c1v.z, rb);
            gb = fmaf(wb, c1v.w, gb);
            bb = fmaf(wb, cbv,  bb);
            Tb -= wb;
        }

        // ---- combine 16 depth segments ----
        int pix0 = row8 * 8 + col8;           // 0..31
        int pix1 = pix0 + 32;                 // rows 4..7
        comb[wid][pix0] = make_float4(ra, ga, ba, Ta);
        comb[wid][pix1] = make_float4(rb, gb, bb, Tb);
        __syncthreads();

        if (wid == 0) {
#pragma unroll 2
            for (int h = 0; h < 2; h++) {
                int pix = lane + h * 32;
                float Tt = 1.f, rr = 0.f, gg = 0.f, bz = 0.f;
#pragma unroll
                for (int ss = 0; ss < 16; ss++) {
                    float4 f = comb[ss][pix];
                    rr = fmaf(Tt, f.x, rr);
                    gg = fmaf(Tt, f.y, gg);
                    bz = fmaf(Tt, f.z, bz);
                    Tt *= f.w;
                }
                int prow = ty * 8 + (pix >> 3);
                int pcol = tx * 8 + (pix & 7);
                int p = prow * W_IMG + pcol;
                out[p]        = rr;
                out[HW + p]   = gg;
                out[2*HW + p] = bz;
            }
        }
    }
}

// ---------------- launch -----------------------------------------------------
extern "C" void kernel_launch(void* const* d_in, const int* in_sizes, int n_in,
                              void* d_out, int out_size)
{
    const float* pts  = (const float*)d_in[0];
    const float* scl  = (const float*)d_in[1];
    const float* col  = (const float*)d_in[2];
    const float* opa  = (const float*)d_in[3];
    const float* rot  = (const float*)d_in[4];
    const float* view = (const float*)d_in[5];
    const float* proj = (const float*)d_in[6];
    float* out = (float*)d_out;

    static bool attr_set = false;
    if (!attr_set) {
        cudaFuncSetAttribute(k_fused, cudaFuncAttributeMaxDynamicSharedMemorySize,
                             (int)SMEM_BYTES);
        attr_set = true;
    }
    k_fused<<<NB, NT, SMEM_BYTES>>>(pts, scl, col, opa, rot, view, proj, out);
}

// round 14
// speedup vs baseline: 1.4276x; 1.1559x over previous
#include <cuda_runtime.h>
#include <cuda_bf16.h>

#define NG    2048
#define W_IMG 128
#define H_IMG 128
#define HW    16384
#define NB    256         // blocks; 2/SM co-resident (88KB smem) -> barrier safe
#define NT    512         // threads per block -> 32 warps/SM = 8/SMSP

// ---------------- scratch (static device globals) ----------------------------
__device__ float4 g_s0[NG], g_s1[NG];          // depth-sorted params
__device__ float4 g_c[NG];                     // depth-sorted (px,py,R,cb)

__device__ unsigned g_barcnt = 0;
__device__ volatile unsigned g_bargen = 0;

__device__ __forceinline__ void gridbar() {
    __syncthreads();
    if (threadIdx.x == 0) {
        unsigned gen = g_bargen;
        __threadfence();
        unsigned t = atomicAdd(&g_barcnt, 1u);
        if (t == NB - 1) {
            g_barcnt = 0;
            __threadfence();
            g_bargen = gen + 1;
        } else {
            while (g_bargen == gen) { __nanosleep(32); }
        }
    }
    __syncthreads();
}

__device__ __forceinline__ float ex2(float x) {
    float y; asm("ex2.approx.f32 %0, %1;" : "=f"(y) : "f"(x)); return y;
}
__device__ __forceinline__ float lg2(float x) {
    float y; asm("lg2.approx.f32 %0, %1;" : "=f"(y) : "f"(x)); return y;
}
__device__ __forceinline__ float frcp(float x) {
    float y; asm("rcp.approx.f32 %0, %1;" : "=f"(y) : "f"(x)); return y;
}
__device__ __forceinline__ float sig_ap(float x) {
    return frcp(1.0f + ex2(-1.4426950408889634f * x));
}
__device__ __forceinline__ float exp_ap(float x) {
    return ex2(1.4426950408889634f * x);
}
__device__ __forceinline__ unsigned fkey(float f) {
    unsigned u = __float_as_uint(f);
    return (u & 0x80000000u) ? ~u : (u | 0x80000000u);
}

// dynamic smem: keys union per-warp blend buffers
struct SmemBlend {
    float4 b0[16][128];                        // 32 KB
    float4 b1[16][128];                        // 32 KB
    float  b2[16][128];                        //  8 KB
};
union SmemU {
    unsigned long long keys[NG];               // 16 KB (rank)
    SmemBlend bl;                              // 72 KB (blend)
};
#define SMEM_BYTES (sizeof(SmemU))

__global__ void __launch_bounds__(NT) k_fused(
        const float* __restrict__ pts, const float* __restrict__ scl,
        const float* __restrict__ col, const float* __restrict__ opa,
        const float* __restrict__ rot, const float* __restrict__ view,
        const float* __restrict__ proj, float* __restrict__ out)
{
    extern __shared__ char dynsmem[];
    SmemU& sm = *reinterpret_cast<SmemU*>(dynsmem);
    __shared__ float4 comb[16][64];            // 16 KB static (blend combine)
    __shared__ float4 sp0[8], sp1[8];          // prep results (this block's 8)
    __shared__ float2 sp2[8];
    __shared__ int    partial[16];

    int tid  = threadIdx.x;
    int lane = tid & 31;
    int wid  = tid >> 5;

    // ===== phase 1 (overlapped): prep own 8 gaussians  ||  all 2048 keys =====
    if (tid < 8) {
        int i = blockIdx.x * 8 + tid;

        float v[16], pr[16];
#pragma unroll
        for (int k = 0; k < 16; k++) v[k]  = view[k];
#pragma unroll
        for (int k = 0; k < 16; k++) pr[k] = proj[k];

        float p0 = pts[3*i], p1 = pts[3*i+1], p2 = pts[3*i+2];

        float t0 = v[0]*p0 + v[1]*p1 + v[2]*p2  + v[3];
        float t1 = v[4]*p0 + v[5]*p1 + v[6]*p2  + v[7];
        float tz = v[8]*p0 + v[9]*p1 + v[10]*p2 + v[11];

        float q0 = rot[4*i], q1 = rot[4*i+1], q2 = rot[4*i+2], q3 = rot[4*i+3];
        float qn = rsqrtf(q0*q0 + q1*q1 + q2*q2 + q3*q3);
        q0 *= qn; q1 *= qn; q2 *= qn; q3 *= qn;
        float R0 = 1.f - 2.f*(q2*q2 + q3*q3), R1 = 2.f*(q1*q2 - q0*q3), R2 = 2.f*(q1*q3 + q0*q2);
        float R3 = 2.f*(q1*q2 + q0*q3), R4 = 1.f - 2.f*(q1*q1 + q3*q3), R5 = 2.f*(q2*q3 - q0*q1);
        float R6 = 2.f*(q1*q3 - q0*q2), R7 = 2.f*(q2*q3 + q0*q1), R8 = 1.f - 2.f*(q1*q1 + q2*q2);

        float s0 = exp_ap(scl[3*i]), s1 = exp_ap(scl[3*i+1]), s2 = exp_ap(scl[3*i+2]);
        float M0 = R0*s0, M1 = R1*s1, M2 = R2*s2;
        float M3 = R3*s0, M4 = R4*s1, M5 = R5*s2;
        float M6 = R6*s0, M7 = R7*s1, M8 = R8*s2;

        const float fx = 64.f, fy = 64.f;
        float invz = frcp(tz);
        float txz = fminf(fmaxf(t0*invz, -1.3f), 1.3f) * tz;
        float tyz = fminf(fmaxf(t1*invz, -1.3f), 1.3f) * tz;
        float J00 = fx*invz, J02 = -fx*txz*invz*invz;
        float J11 = fy*invz, J12 = -fy*tyz*invz*invz;

        float T00 = J00*v[0] + J02*v[8],  T01 = J00*v[1] + J02*v[9],  T02 = J00*v[2] + J02*v[10];
        float T10 = J11*v[4] + J12*v[8],  T11 = J11*v[5] + J12*v[9],  T12 = J11*v[6] + J12*v[10];

        float X00 = T00*M0 + T01*M3 + T02*M6;
        float X01 = T00*M1 + T01*M4 + T02*M7;
        float X02 = T00*M2 + T01*M5 + T02*M8;
        float X10 = T10*M0 + T11*M3 + T12*M6;
        float X11 = T10*M1 + T11*M4 + T12*M7;
        float X12 = T10*M2 + T11*M5 + T12*M8;

        float a = X00*X00 + X01*X01 + X02*X02 + 0.3f;
        float b = X00*X10 + X01*X11 + X02*X12;
        float c = X10*X10 + X11*X11 + X12*X12 + 0.3f;

        float det   = a*c - b*b;
        bool  valid = (tz > 0.2f) && (det > 0.0f);
        float det_s = (det > 0.0f) ? det : 1.0f;
        float idet  = frcp(det_s);

        const float L2E = 1.4426950408889634f;
        float A2 = -0.5f * c * idet * L2E;
        float C2 = -0.5f * a * idet * L2E;
        float Bq =         b * idet * L2E;

        float mid   = 0.5f * (a + c);
        float lam   = mid + sqrtf(fmaxf(mid*mid - det, 0.1f));
        float sq    = sqrtf(lam);
        float radii = valid ? ceilf(3.0f * sq) : 0.0f;

        float op = valid ? sig_ap(opa[i]) : 0.0f;
        // opacity-aware cull radius: alpha = op*exp(-d^2/(2*lam)) < 1/255 beyond
        float lnt   = 0.6931471805599453f * lg2(255.0f * fmaxf(op, 1e-30f));
        float cullR = (valid && lnt > 0.f) ? 1.001f * sqrtf(2.0f * lnt) * sq : 0.0f;

        float fr0[4], fr1[4], fr3[4];
#pragma unroll
        for (int cc = 0; cc < 4; cc++) {
            fr0[cc] = pr[0]*v[cc]  + pr[1]*v[4+cc]  + pr[2]*v[8+cc]  + pr[3]*v[12+cc];
            fr1[cc] = pr[4]*v[cc]  + pr[5]*v[4+cc]  + pr[6]*v[8+cc]  + pr[7]*v[12+cc];
            fr3[cc] = pr[12]*v[cc] + pr[13]*v[4+cc] + pr[14]*v[8+cc] + pr[15]*v[12+cc];
        }
        float ph0 = fr0[0]*p0 + fr0[1]*p1 + fr0[2]*p2 + fr0[3];
        float ph1 = fr1[0]*p0 + fr1[1]*p1 + fr1[2]*p2 + fr1[3];
        float ph3 = fr3[0]*p0 + fr3[1]*p1 + fr3[2]*p2 + fr3[3];
        float pwn = frcp(ph3 + 1e-7f);
        float px  = ((ph0*pwn + 1.0f) * (float)W_IMG - 1.0f) * 0.5f;
        float py  = ((ph1*pwn + 1.0f) * (float)H_IMG - 1.0f) * 0.5f;

        float cr = sig_ap(col[3*i]);
        float cg = sig_ap(col[3*i+1]);
        float cb = sig_ap(col[3*i+2]);

        sp0[tid] = make_float4(px, py, A2, Bq);
        sp1[tid] = make_float4(C2, op, cr, cg);
        sp2[tid] = make_float2(cb, cullR);

        out[3*HW + i]      = radii;
        out[3*HW + NG + i] = tz;
    } else if (tid >= 32) {
        // block-local keys for ALL gaussians (identical across blocks)
        float v8 = view[8], v9 = view[9], v10 = view[10], v11 = view[11];
        for (int g2 = tid - 32; g2 < NG; g2 += NT - 32) {
            float tzk = fmaf(v8, pts[3*g2],
                        fmaf(v9, pts[3*g2+1],
                        fmaf(v10, pts[3*g2+2], v11)));
            sm.keys[g2] = ((unsigned long long)fkey(tzk) << 32) | (unsigned)g2;
        }
    }
    __syncthreads();   // prep done (smem sp*), keys done (smem keys)

    // ===== phase 2: rank own 8 gaussians (16 warps: 2 per gaussian) ==========
    {
        int g8   = wid & 7;                   // gaussian within block
        int half = wid >> 3;                  // key half [half*1024, +1024)
        int gi   = blockIdx.x * 8 + g8;
        unsigned long long ki = sm.keys[gi];

        int rk = 0;
        int kb = half * 1024;
#pragma unroll 8
        for (int it = 0; it < 32; it++) {
            rk += (sm.keys[kb + it * 32 + lane] < ki) ? 1 : 0;
        }
        rk += __shfl_xor_sync(0xffffffffu, rk, 1);
        rk += __shfl_xor_sync(0xffffffffu, rk, 2);
        rk += __shfl_xor_sync(0xffffffffu, rk, 4);
        rk += __shfl_xor_sync(0xffffffffu, rk, 8);
        rk += __shfl_xor_sync(0xffffffffu, rk, 16);
        if (lane == 0) partial[wid] = rk;
    }
    __syncthreads();

    if (wid < 8 && lane == 0) {
        int rk = partial[wid] + partial[wid + 8];
        float4 p0v = sp0[wid];
        float2 p2v = sp2[wid];
        g_s0[rk] = p0v;
        g_s1[rk] = sp1[wid];
        g_c[rk]  = make_float4(p0v.x, p0v.y, p2v.y, p2v.x);  // (px,py,R,cb)
    }

    gridbar();   // the ONLY grid barrier

    // ==== phase 3: blend, 8x8 tile, warp = 128-gaussian depth segment ========
    {
        unsigned lmask = (1u << lane) - 1u;
        int base = wid * 128;

        int tx = blockIdx.x & 15;            // 16 tiles across
        int ty = blockIdx.x >> 4;            // 16 tiles down
        // 2 pixels per lane, same column: rows (lane>>3) and (lane>>3)+4
        int col8 = lane & 7;
        int row8 = lane >> 3;
        int pxi  = tx * 8 + col8;
        int pyi0 = ty * 8 + row8;
        float x  = (float)pxi;
        float ya = (float)pyi0;
        float yb = ya + 4.f;
        float x0 = (float)(tx * 8), x1 = x0 + 7.f;
        float y0 = (float)(ty * 8), y1 = y0 + 7.f;

        // ---- warp-local cull: 4 gaussians per lane, one LDG.128 each ----
        unsigned mk[4];
#pragma unroll
        for (int kk = 0; kk < 4; kk++) {
            int gidx = base + kk * 32 + lane;
            float4 cc = g_c[gidx];           // (px,py,R,cb)
            float dxc = fmaxf(fmaxf(x0 - cc.x, cc.x - x1), 0.f);
            float dyc = fmaxf(fmaxf(y0 - cc.y, cc.y - y1), 0.f);
            bool p = (cc.z > 0.f) && (dxc*dxc + dyc*dyc <= cc.z*cc.z);
            mk[kk] = __ballot_sync(0xffffffffu, p);
        }

        int pre = 0;
#pragma unroll
        for (int kk = 0; kk < 4; kk++) {
            unsigned m = mk[kk];
            if (m & (1u << lane)) {
                int gidx = base + kk * 32 + lane;
                int pp   = pre + __popc(m & lmask);
                sm.bl.b0[wid][pp] = g_s0[gidx];
                sm.bl.b1[wid][pp] = g_s1[gidx];
                sm.bl.b2[wid][pp] = g_c[gidx].w;   // cb, L1-hot reload
            }
            pre += __popc(m);
        }
        int cnt = pre;
        __syncwarp();

        // ---- blend survivors for 2 pixels (independent T-chains) ----
        float ra = 0.f, ga = 0.f, ba = 0.f, Ta = 1.f;
        float rb = 0.f, gb = 0.f, bb = 0.f, Tb = 1.f;
#pragma unroll 2
        for (int n = 0; n < cnt; n++) {
            float4 c0v = sm.bl.b0[wid][n];
            float4 c1v = sm.bl.b1[wid][n];
            float  cbv = sm.bl.b2[wid][n];
            float dx   = x - c0v.x;
            float com  = (c0v.z * dx) * dx;   // A2*dx^2 shared
            float crs  = c0v.w * dx;          // Bq*dx  shared

            float dya = ya - c0v.y;
            float pwa = fmaf(c1v.x * dya, dya, fmaf(crs, dya, com));
            float ea  = ex2(pwa);
            float ala = fminf(c1v.y * ea, 0.99f);
            float wa  = ((pwa <= 0.0f) && (ala >= 0.0039215686f)) ? Ta * ala : 0.0f;
            ra = fmaf(wa, c1v.z, ra);
            ga = fmaf(wa, c1v.w, ga);
            ba = fmaf(wa, cbv,  ba);
            Ta -= wa;

            float dyb = yb - c0v.y;
            float pwb = fmaf(c1v.x * dyb, dyb, fmaf(crs, dyb, com));
            float eb  = ex2(pwb);
            float alb = fminf(c1v.y * eb, 0.99f);
            float wb  = ((pwb <= 0.0f) && (alb >= 0.0039215686f)) ? Tb * alb : 0.0f;
            rb = fmaf(wb, c1v.z, rb);
            gb = fmaf(wb, c1v.w, gb);
            bb = fmaf(wb, cbv,  bb);
            Tb -= wb;
        }

        // ---- combine 16 depth segments ----
        int pix0 = row8 * 8 + col8;           // 0..31
        int pix1 = pix0 + 32;                 // rows 4..7
        comb[wid][pix0] = make_float4(ra, ga, ba, Ta);
        comb[wid][pix1] = make_float4(rb, gb, bb, Tb);
        __syncthreads();

        if (wid == 0) {
#pragma unroll 2
            for (int h = 0; h < 2; h++) {
                int pix = lane + h * 32;
                float Tt = 1.f, rr = 0.f, gg = 0.f, bz = 0.f;
#pragma unroll
                for (int ss = 0; ss < 16; ss++) {
                    float4 f = comb[ss][pix];
                    rr = fmaf(Tt, f.x, rr);
                    gg = fmaf(Tt, f.y, gg);
                    bz = fmaf(Tt, f.z, bz);
                    Tt *= f.w;
                }
                int prow = ty * 8 + (pix >> 3);
                int pcol = tx * 8 + (pix & 7);
                int p = prow * W_IMG + pcol;
                out[p]        = rr;
                out[HW + p]   = gg;
                out[2*HW + p] = bz;
            }
        }
    }
}

// ---------------- launch -----------------------------------------------------
extern "C" void kernel_launch(void* const* d_in, const int* in_sizes, int n_in,
                              void* d_out, int out_size)
{
    const float* pts  = (const float*)d_in[0];
    const float* scl  = (const float*)d_in[1];
    const float* col  = (const float*)d_in[2];
    const float* opa  = (const float*)d_in[3];
    const float* rot  = (const float*)d_in[4];
    const float* view = (const float*)d_in[5];
    const float* proj = (const float*)d_in[6];
    float* out = (float*)d_out;

    static bool attr_set = false;
    if (!attr_set) {
        cudaFuncSetAttribute(k_fused, cudaFuncAttributeMaxDynamicSharedMemorySize,
                             (int)SMEM_BYTES);
        attr_set = true;
    }
    k_fused<<<NB, NT, SMEM_BYTES>>>(pts, scl, col, opa, rot, view, proj, out);
}